// round 1
// baseline (speedup 1.0000x reference)
#include <cuda_runtime.h>
#include <float.h>

#define N_NODES 588
#define K_DEG   32
#define NBLK    148
#define NTHR    256
#define NWARPS  (NTHR/32)
#define GWARPS  (NBLK*NWARPS)   // 1184

// -------- global scratch (allocation-free: __device__ arrays) --------
__device__ __align__(16) float g_act3[256];
__device__ __align__(16) float g_act4[512];
__device__ __align__(16) float g_act5[1024];
__device__ unsigned g_bar_cnt = 0;
__device__ volatile unsigned g_bar_gen = 0;

__device__ __forceinline__ float lrelu(float x) { return x > 0.f ? x : 0.01f * x; }

// Generation-counting grid barrier. Self-resetting (count returns to 0, gen
// monotonically increases), so state is consistent across graph replays.
// Safe: grid (148 x 256thr, ~29KB smem) is always fully co-resident.
__device__ __forceinline__ void grid_bar() {
    __syncthreads();
    if (threadIdx.x == 0) {
        __threadfence();                       // release my writes
        unsigned gen = g_bar_gen;
        if (atomicAdd(&g_bar_cnt, 1u) == NBLK - 1) {
            g_bar_cnt = 0;
            __threadfence();
            g_bar_gen = gen + 1;               // release
        } else {
            while (g_bar_gen == gen) { }       // volatile L2 poll
            __threadfence();                   // acquire
        }
    }
    __syncthreads();
}

__device__ __forceinline__ float warp_sum(float v) {
#pragma unroll
    for (int o = 16; o; o >>= 1) v += __shfl_xor_sync(0xffffffffu, v, o);
    return v;
}

__global__ void __launch_bounds__(NTHR, 1) fused_try10(
    const float* __restrict__ features, const int* __restrict__ src,
    const float* __restrict__ t1w, const float* __restrict__ t1b,
    const float* __restrict__ p1w, const float* __restrict__ p1b,
    const float* __restrict__ t2w, const float* __restrict__ t2b,
    const float* __restrict__ p2w, const float* __restrict__ p2b,
    const float* __restrict__ fc1w, const float* __restrict__ fc1b,
    const float* __restrict__ fc2w, const float* __restrict__ fc2b,
    const float* __restrict__ fc3w, const float* __restrict__ fc3b,
    const float* __restrict__ fc4w, const float* __restrict__ fc4b,
    const float* __restrict__ fc5w, const float* __restrict__ fc5b,
    const float* __restrict__ fc6w, const float* __restrict__ fc6b,
    float* __restrict__ out)
{
    const int tid  = threadIdx.x;
    const int bid  = blockIdx.x;
    const int warp = tid >> 5;
    const int lane = tid & 31;

    // ---------------- Phase A: block 0 only — EC1, EC2, fc1..fc3 ----------------
    if (bid == 0) {
        __shared__ float a1[N_NODES * 3], c1[N_NODES * 3], x1[N_NODES * 3];
        __shared__ float a2[N_NODES], c2[N_NODES], x2[N_NODES];
        __shared__ float y10[10];
        __shared__ float y128[128];

        // EdgeConv1 decomposition: msg = a1[src] + c1[dst]
        float T1[9], P1[9], B1[3];
#pragma unroll
        for (int i = 0; i < 9; i++) { T1[i] = t1w[i]; P1[i] = p1w[i]; }
#pragma unroll
        for (int i = 0; i < 3; i++) B1[i] = t1b[i] + p1b[i];

        for (int j = tid; j < N_NODES; j += NTHR) {
            float v0 = features[j * 3], v1 = features[j * 3 + 1], v2 = features[j * 3 + 2];
#pragma unroll
            for (int k = 0; k < 3; k++) {
                float av = T1[k * 3] * v0 + T1[k * 3 + 1] * v1 + T1[k * 3 + 2] * v2;
                float pv = P1[k * 3] * v0 + P1[k * 3 + 1] * v1 + P1[k * 3 + 2] * v2;
                a1[j * 3 + k] = av;
                c1[j * 3 + k] = B1[k] + pv - av;
            }
        }
        __syncthreads();

        // segment-max over the 32 incoming edges of node i (dst = i, rows sorted)
        for (int i = tid; i < N_NODES; i += NTHR) {
            float m0 = -FLT_MAX, m1 = -FLT_MAX, m2 = -FLT_MAX;
            const int* sp = src + i * K_DEG;
#pragma unroll 8
            for (int e = 0; e < K_DEG; e++) {
                int s = sp[e] * 3;
                m0 = fmaxf(m0, a1[s]);
                m1 = fmaxf(m1, a1[s + 1]);
                m2 = fmaxf(m2, a1[s + 2]);
            }
            x1[i * 3]     = m0 + c1[i * 3];
            x1[i * 3 + 1] = m1 + c1[i * 3 + 1];
            x1[i * 3 + 2] = m2 + c1[i * 3 + 2];
        }
        __syncthreads();

        // EdgeConv2 (out dim 1)
        float T2[3], P2[3];
#pragma unroll
        for (int i = 0; i < 3; i++) { T2[i] = t2w[i]; P2[i] = p2w[i]; }
        float B2 = t2b[0] + p2b[0];
        for (int j = tid; j < N_NODES; j += NTHR) {
            float v0 = x1[j * 3], v1 = x1[j * 3 + 1], v2 = x1[j * 3 + 2];
            float av = T2[0] * v0 + T2[1] * v1 + T2[2] * v2;
            a2[j] = av;
            c2[j] = B2 + P2[0] * v0 + P2[1] * v1 + P2[2] * v2 - av;
        }
        __syncthreads();
        for (int i = tid; i < N_NODES; i += NTHR) {
            float m = -FLT_MAX;
            const int* sp = src + i * K_DEG;
#pragma unroll 8
            for (int e = 0; e < K_DEG; e++) m = fmaxf(m, a2[sp[e]]);
            x2[i] = m + c2[i];
        }
        __syncthreads();

        // fc1: [588] -> [10], warp-per-output
        for (int k = warp; k < 10; k += NWARPS) {
            float acc = 0.f;
            for (int j = lane; j < N_NODES; j += 32) acc += x2[j] * fc1w[k * N_NODES + j];
            acc = warp_sum(acc);
            if (lane == 0) y10[k] = lrelu(acc + fc1b[k]);
        }
        __syncthreads();

        // fc2: [10] -> [128]
        if (tid < 128) {
            float acc = fc2b[tid];
#pragma unroll
            for (int j = 0; j < 10; j++) acc += y10[j] * fc2w[tid * 10 + j];
            y128[tid] = lrelu(acc);
        }
        __syncthreads();

        // fc3: [128] -> [256], thread-per-output with 4 accumulators
        {
            float a0 = 0.f, b0 = 0.f, c0 = 0.f, d0 = 0.f;
            const float* wr = fc3w + tid * 128;
#pragma unroll
            for (int j = 0; j < 128; j += 4) {
                a0 += y128[j]     * wr[j];
                b0 += y128[j + 1] * wr[j + 1];
                c0 += y128[j + 2] * wr[j + 2];
                d0 += y128[j + 3] * wr[j + 3];
            }
            g_act3[tid] = lrelu(((a0 + b0) + (c0 + d0)) + fc3b[tid]);
        }
    }
    grid_bar();

    // ---------------- Phase B: fc4 [256]->[512], warp-per-output ----------------
    {
        int gw = bid * NWARPS + warp;           // 0..1183
        if (gw < 512) {
            const float4* wr = (const float4*)(fc4w + gw * 256);
            const float4* ar = (const float4*)g_act3;
            float acc = 0.f;
#pragma unroll
            for (int it = 0; it < 2; it++) {
                float4 w4 = wr[lane + 32 * it];
                float4 a4 = ar[lane + 32 * it];
                acc += w4.x * a4.x + w4.y * a4.y + w4.z * a4.z + w4.w * a4.w;
            }
            acc = warp_sum(acc);
            if (lane == 0) g_act4[gw] = lrelu(acc + fc4b[gw]);
        }
    }
    grid_bar();

    // ---------------- Phase C: fc5 [512]->[1024] ----------------
    {
        int gw = bid * NWARPS + warp;
        if (gw < 1024) {
            const float4* wr = (const float4*)(fc5w + gw * 512);
            const float4* ar = (const float4*)g_act4;
            float acc = 0.f;
#pragma unroll
            for (int it = 0; it < 4; it++) {
                float4 w4 = wr[lane + 32 * it];
                float4 a4 = ar[lane + 32 * it];
                acc += w4.x * a4.x + w4.y * a4.y + w4.z * a4.z + w4.w * a4.w;
            }
            acc = warp_sum(acc);
            if (lane == 0) g_act5[gw] = lrelu(acc + fc5b[gw]);
        }
    }
    grid_bar();

    // ---------------- Phase D: fc6 [1024]->[1764], no activation ----------------
    {
        int gw = bid * NWARPS + warp;
        for (int k = gw; k < 1764; k += GWARPS) {
            const float4* wr = (const float4*)(fc6w + (size_t)k * 1024);
            const float4* ar = (const float4*)g_act5;
            float acc = 0.f;
#pragma unroll
            for (int it = 0; it < 8; it++) {
                float4 w4 = wr[lane + 32 * it];
                float4 a4 = ar[lane + 32 * it];
                acc += w4.x * a4.x + w4.y * a4.y + w4.z * a4.z + w4.w * a4.w;
            }
            acc = warp_sum(acc);
            if (lane == 0) out[k] = acc + fc6b[k];
        }
    }
}

extern "C" void kernel_launch(void* const* d_in, const int* in_sizes, int n_in,
                              void* d_out, int out_size) {
    // metadata order:
    // 0 features, 1 src, 2 dst (unused: dst[e] == e/32 by construction),
    // 3 theta1_w, 4 theta1_b, 5 phi1_w, 6 phi1_b,
    // 7 theta2_w, 8 theta2_b, 9 phi2_w, 10 phi2_b,
    // 11 fc1_w, 12 fc1_b, 13 fc2_w, 14 fc2_b, 15 fc3_w, 16 fc3_b,
    // 17 fc4_w, 18 fc4_b, 19 fc5_w, 20 fc5_b, 21 fc6_w, 22 fc6_b
    fused_try10<<<NBLK, NTHR>>>(
        (const float*)d_in[0], (const int*)d_in[1],
        (const float*)d_in[3], (const float*)d_in[4],
        (const float*)d_in[5], (const float*)d_in[6],
        (const float*)d_in[7], (const float*)d_in[8],
        (const float*)d_in[9], (const float*)d_in[10],
        (const float*)d_in[11], (const float*)d_in[12],
        (const float*)d_in[13], (const float*)d_in[14],
        (const float*)d_in[15], (const float*)d_in[16],
        (const float*)d_in[17], (const float*)d_in[18],
        (const float*)d_in[19], (const float*)d_in[20],
        (const float*)d_in[21], (const float*)d_in[22],
        (float*)d_out);
}

// round 3
// speedup vs baseline: 1.3390x; 1.3390x over previous
#include <cuda_runtime.h>
#include <float.h>

#define N_NODES 588
#define K_DEG   32
#define NBLK    148
#define NTHR    256
#define NWARPS  (NTHR/32)
#define GWARPS  (NBLK*NWARPS)   // 1184

// -------- global scratch (allocation-free: __device__ arrays) --------
__device__ __align__(16) float g_act3[256];
__device__ __align__(16) float g_act4[512];
__device__ __align__(16) float g_act5[1024];
__device__ unsigned g_bar_cnt = 0;
__device__ volatile unsigned g_bar_gen = 0;

__device__ __forceinline__ float lrelu(float x) { return x > 0.f ? x : 0.01f * x; }

// Generation-counting grid barrier, self-resetting across graph replays.
// Grid is 148 blocks x 256 thr at 1 block/SM -> always fully co-resident.
__device__ __forceinline__ void grid_bar() {
    __threadfence();                           // release prior global writes (all threads)
    __syncthreads();
    if (threadIdx.x == 0) {
        unsigned gen = g_bar_gen;
        if (atomicAdd(&g_bar_cnt, 1u) == NBLK - 1) {
            g_bar_cnt = 0;
            __threadfence();
            g_bar_gen = gen + 1;               // release
        } else {
            while (g_bar_gen == gen) { }       // L2 poll
        }
    }
    __syncthreads();
    __threadfence();                           // acquire
}

__device__ __forceinline__ float warp_sum(float v) {
#pragma unroll
    for (int o = 16; o; o >>= 1) v += __shfl_xor_sync(0xffffffffu, v, o);
    return v;
}

__device__ __forceinline__ void l2_prefetch_stripe(const float* p, int n_floats,
                                                   int idx, int stride) {
    int lines = (n_floats + 31) >> 5;          // 128B lines
    for (int l = idx; l < lines; l += stride)
        asm volatile("prefetch.global.L2 [%0];" :: "l"(p + l * 32));
}

__global__ void __launch_bounds__(NTHR, 1) fused_try10(
    const float* __restrict__ features, const int* __restrict__ src,
    const float* __restrict__ t1w, const float* __restrict__ t1b,
    const float* __restrict__ p1w, const float* __restrict__ p1b,
    const float* __restrict__ t2w, const float* __restrict__ t2b,
    const float* __restrict__ p2w, const float* __restrict__ p2b,
    const float* __restrict__ fc1w, const float* __restrict__ fc1b,
    const float* __restrict__ fc2w, const float* __restrict__ fc2b,
    const float* __restrict__ fc3w, const float* __restrict__ fc3b,
    const float* __restrict__ fc4w, const float* __restrict__ fc4b,
    const float* __restrict__ fc5w, const float* __restrict__ fc5b,
    const float* __restrict__ fc6w, const float* __restrict__ fc6b,
    float* __restrict__ out)
{
    const int tid  = threadIdx.x;
    const int bid  = blockIdx.x;
    const int warp = tid >> 5;
    const int lane = tid & 31;

    // ---------------- Phase A: block 0 — EC1, EC2, fc1..fc3 ----------------
    if (bid == 0) {
        __shared__ float a1[N_NODES * 3], c1[N_NODES * 3], x1[N_NODES * 3];
        __shared__ float a2[N_NODES], c2[N_NODES], x2[N_NODES];
        __shared__ float y10[10];
        __shared__ __align__(16) float y128[128];

        // EdgeConv1 decomposition: msg = a1[src] + c1[dst]; max commutes with +c
        float T1[9], P1[9], B1[3];
#pragma unroll
        for (int i = 0; i < 9; i++) { T1[i] = t1w[i]; P1[i] = p1w[i]; }
#pragma unroll
        for (int i = 0; i < 3; i++) B1[i] = t1b[i] + p1b[i];

        for (int j = tid; j < N_NODES; j += NTHR) {
            float v0 = features[j * 3], v1 = features[j * 3 + 1], v2 = features[j * 3 + 2];
#pragma unroll
            for (int k = 0; k < 3; k++) {
                float av = T1[k * 3] * v0 + T1[k * 3 + 1] * v1 + T1[k * 3 + 2] * v2;
                float pv = P1[k * 3] * v0 + P1[k * 3 + 1] * v1 + P1[k * 3 + 2] * v2;
                a1[j * 3 + k] = av;
                c1[j * 3 + k] = B1[k] + pv - av;
            }
        }
        __syncthreads();

        // segment-max over the 32 incoming edges of node i (dst rows sorted)
        for (int i = tid; i < N_NODES; i += NTHR) {
            float m0 = -FLT_MAX, m1 = -FLT_MAX, m2 = -FLT_MAX;
            const int* sp = src + i * K_DEG;
#pragma unroll
            for (int e = 0; e < K_DEG; e++) {
                int s = sp[e] * 3;
                m0 = fmaxf(m0, a1[s]);
                m1 = fmaxf(m1, a1[s + 1]);
                m2 = fmaxf(m2, a1[s + 2]);
            }
            x1[i * 3]     = m0 + c1[i * 3];
            x1[i * 3 + 1] = m1 + c1[i * 3 + 1];
            x1[i * 3 + 2] = m2 + c1[i * 3 + 2];
        }
        __syncthreads();

        // EdgeConv2 (out dim 1)
        float T2[3], P2[3];
#pragma unroll
        for (int i = 0; i < 3; i++) { T2[i] = t2w[i]; P2[i] = p2w[i]; }
        float B2 = t2b[0] + p2b[0];
        for (int j = tid; j < N_NODES; j += NTHR) {
            float v0 = x1[j * 3], v1 = x1[j * 3 + 1], v2 = x1[j * 3 + 2];
            float av = T2[0] * v0 + T2[1] * v1 + T2[2] * v2;
            a2[j] = av;
            c2[j] = B2 + P2[0] * v0 + P2[1] * v1 + P2[2] * v2 - av;
        }
        __syncthreads();
        for (int i = tid; i < N_NODES; i += NTHR) {
            float m = -FLT_MAX;
            const int* sp = src + i * K_DEG;
#pragma unroll
            for (int e = 0; e < K_DEG; e++) m = fmaxf(m, a2[sp[e]]);
            x2[i] = m + c2[i];
        }
        __syncthreads();

        // fc1: [588] -> [10], warp-per-output (coalesced 4B lanes)
        for (int k = warp; k < 10; k += NWARPS) {
            float acc = 0.f;
            for (int j = lane; j < N_NODES; j += 32) acc += x2[j] * fc1w[k * N_NODES + j];
            acc = warp_sum(acc);
            if (lane == 0) y10[k] = lrelu(acc + fc1b[k]);
        }
        __syncthreads();

        // fc2: [10] -> [128]
        if (tid < 128) {
            float acc = fc2b[tid];
#pragma unroll
            for (int j = 0; j < 10; j++) acc += y10[j] * fc2w[tid * 10 + j];
            y128[tid] = lrelu(acc);
        }
        __syncthreads();

        // fc3: [128] -> [256]. Warp-per-output, float4-coalesced, 8 outputs in
        // flight per pass (each output = exactly one float4 per lane).
        {
            float4 a4 = ((const float4*)y128)[lane];
#pragma unroll
            for (int pass = 0; pass < 4; pass++) {
                int kb = warp * 32 + pass * 8;
                float acc[8];
#pragma unroll
                for (int q = 0; q < 8; q++) {
                    float4 w4 = *((const float4*)(fc3w + (kb + q) * 128) + lane);
                    acc[q] = w4.x * a4.x + w4.y * a4.y + w4.z * a4.z + w4.w * a4.w;
                }
#pragma unroll
                for (int q = 0; q < 8; q++) acc[q] = warp_sum(acc[q]);
                if (lane == 0) {
#pragma unroll
                    for (int q = 0; q < 8; q++)
                        g_act3[kb + q] = lrelu(acc[q] + fc3b[kb + q]);
                }
            }
        }
    } else {
        // Blocks 1..147: pull all downstream FC weights into L2 while block 0
        // runs the serial graph/MLP-head phase. Fully overlapped.
        int idx    = (bid - 1) * NTHR + tid;
        int stride = (NBLK - 1) * NTHR;
        l2_prefetch_stripe(fc4w, 512 * 256,    idx, stride);
        l2_prefetch_stripe(fc5w, 1024 * 512,   idx, stride);
        l2_prefetch_stripe(fc6w, 1764 * 1024,  idx, stride);
        l2_prefetch_stripe(fc6b, 1764,         idx, stride);
    }
    grid_bar();

    // ---------------- Phase B: fc4 [256]->[512], warp-per-output ----------------
    {
        int gw = bid * NWARPS + warp;           // 0..1183
        if (gw < 512) {
            const float4* wr = (const float4*)(fc4w + gw * 256);
            const float4* ar = (const float4*)g_act3;
            float acc = 0.f;
#pragma unroll
            for (int it = 0; it < 2; it++) {
                float4 w4 = wr[lane + 32 * it];
                float4 a4 = ar[lane + 32 * it];
                acc += w4.x * a4.x + w4.y * a4.y + w4.z * a4.z + w4.w * a4.w;
            }
            acc = warp_sum(acc);
            if (lane == 0) g_act4[gw] = lrelu(acc + fc4b[gw]);
        }
    }
    grid_bar();

    // ---------------- Phase C: fc5 [512]->[1024] ----------------
    {
        int gw = bid * NWARPS + warp;
        if (gw < 1024) {
            const float4* wr = (const float4*)(fc5w + gw * 512);
            const float4* ar = (const float4*)g_act4;
            float acc = 0.f;
#pragma unroll
            for (int it = 0; it < 4; it++) {
                float4 w4 = wr[lane + 32 * it];
                float4 a4 = ar[lane + 32 * it];
                acc += w4.x * a4.x + w4.y * a4.y + w4.z * a4.z + w4.w * a4.w;
            }
            acc = warp_sum(acc);
            if (lane == 0) g_act5[gw] = lrelu(acc + fc5b[gw]);
        }
    }
    grid_bar();

    // ---------------- Phase D: fc6 [1024]->[1764], two outputs, branch-free ----------------
    {
        int gw = bid * NWARPS + warp;
        int k0 = gw;                             // < 1764 always (gw <= 1183)
        int k1 = gw + GWARPS;                    // valid output iff < 1764
        bool two = (k1 < 1764);
        int k1c = two ? k1 : k0;                 // clamp: always in-bounds row

        const float4* ar = (const float4*)g_act5;
        float4 A[8];
#pragma unroll
        for (int it = 0; it < 8; it++) A[it] = ar[lane + 32 * it];

        const float4* w0 = (const float4*)(fc6w + (size_t)k0 * 1024);
        const float4* w1 = (const float4*)(fc6w + (size_t)k1c * 1024);
        float acc0 = 0.f, acc1 = 0.f;
#pragma unroll
        for (int it = 0; it < 8; it++) {
            float4 wa = w0[lane + 32 * it];
            float4 wb = w1[lane + 32 * it];
            acc0 += wa.x * A[it].x + wa.y * A[it].y + wa.z * A[it].z + wa.w * A[it].w;
            acc1 += wb.x * A[it].x + wb.y * A[it].y + wb.z * A[it].z + wb.w * A[it].w;
        }
        acc0 = warp_sum(acc0);
        acc1 = warp_sum(acc1);
        if (lane == 0) {
            out[k0] = acc0 + fc6b[k0];
            if (two) out[k1] = acc1 + fc6b[k1];
        }
    }
}

extern "C" void kernel_launch(void* const* d_in, const int* in_sizes, int n_in,
                              void* d_out, int out_size) {
    // metadata order:
    // 0 features, 1 src, 2 dst (unused: dst[e] == e/32 by construction),
    // 3 theta1_w, 4 theta1_b, 5 phi1_w, 6 phi1_b,
    // 7 theta2_w, 8 theta2_b, 9 phi2_w, 10 phi2_b,
    // 11 fc1_w, 12 fc1_b, 13 fc2_w, 14 fc2_b, 15 fc3_w, 16 fc3_b,
    // 17 fc4_w, 18 fc4_b, 19 fc5_w, 20 fc5_b, 21 fc6_w, 22 fc6_b
    fused_try10<<<NBLK, NTHR>>>(
        (const float*)d_in[0], (const int*)d_in[1],
        (const float*)d_in[3], (const float*)d_in[4],
        (const float*)d_in[5], (const float*)d_in[6],
        (const float*)d_in[7], (const float*)d_in[8],
        (const float*)d_in[9], (const float*)d_in[10],
        (const float*)d_in[11], (const float*)d_in[12],
        (const float*)d_in[13], (const float*)d_in[14],
        (const float*)d_in[15], (const float*)d_in[16],
        (const float*)d_in[17], (const float*)d_in[18],
        (const float*)d_in[19], (const float*)d_in[20],
        (const float*)d_in[21], (const float*)d_in[22],
        (float*)d_out);
}

// round 4
// speedup vs baseline: 1.4811x; 1.1061x over previous
#include <cuda_runtime.h>
#include <float.h>

#define N_NODES 588
#define K_DEG   32

// -------- global scratch (allocation-free: __device__ arrays) --------
__device__ __align__(16) float g_act3[256];
__device__ __align__(16) float g_act4[512];
__device__ __align__(16) float g_act5[1024];

__device__ __forceinline__ float lrelu(float x) { return x > 0.f ? x : 0.01f * x; }

__device__ __forceinline__ float warp_sum(float v) {
#pragma unroll
    for (int o = 16; o; o >>= 1) v += __shfl_xor_sync(0xffffffffu, v, o);
    return v;
}

// ================= K1: EC1 + EC2 + fc1 + fc2 + fc3 (single block) =================
__global__ void __launch_bounds__(256, 1) k_head(
    const float* __restrict__ features, const int* __restrict__ src,
    const float* __restrict__ t1w, const float* __restrict__ t1b,
    const float* __restrict__ p1w, const float* __restrict__ p1b,
    const float* __restrict__ t2w, const float* __restrict__ t2b,
    const float* __restrict__ p2w, const float* __restrict__ p2b,
    const float* __restrict__ fc1w, const float* __restrict__ fc1b,
    const float* __restrict__ fc2w, const float* __restrict__ fc2b,
    const float* __restrict__ fc3w, const float* __restrict__ fc3b)
{
    const int tid  = threadIdx.x;
    const int warp = tid >> 5;
    const int lane = tid & 31;

    __shared__ float a1[N_NODES * 3], c1[N_NODES * 3], x1[N_NODES * 3];
    __shared__ float a2[N_NODES], c2[N_NODES], x2[N_NODES];
    __shared__ float y10[10];
    __shared__ __align__(16) float y128[128];

    // EdgeConv1 decomposition: msg = a1[src] + c1[dst]; max commutes with +c
    float T1[9], P1[9], B1[3];
#pragma unroll
    for (int i = 0; i < 9; i++) { T1[i] = t1w[i]; P1[i] = p1w[i]; }
#pragma unroll
    for (int i = 0; i < 3; i++) B1[i] = t1b[i] + p1b[i];

    for (int j = tid; j < N_NODES; j += 256) {
        float v0 = features[j * 3], v1 = features[j * 3 + 1], v2 = features[j * 3 + 2];
#pragma unroll
        for (int k = 0; k < 3; k++) {
            float av = T1[k * 3] * v0 + T1[k * 3 + 1] * v1 + T1[k * 3 + 2] * v2;
            float pv = P1[k * 3] * v0 + P1[k * 3 + 1] * v1 + P1[k * 3 + 2] * v2;
            a1[j * 3 + k] = av;
            c1[j * 3 + k] = B1[k] + pv - av;
        }
    }
    __syncthreads();

    // segment-max over the 32 incoming edges of node i (dst rows sorted)
    for (int i = tid; i < N_NODES; i += 256) {
        float m0 = -FLT_MAX, m1 = -FLT_MAX, m2 = -FLT_MAX;
        const int* sp = src + i * K_DEG;
#pragma unroll
        for (int e = 0; e < K_DEG; e++) {
            int s = sp[e] * 3;
            m0 = fmaxf(m0, a1[s]);
            m1 = fmaxf(m1, a1[s + 1]);
            m2 = fmaxf(m2, a1[s + 2]);
        }
        x1[i * 3]     = m0 + c1[i * 3];
        x1[i * 3 + 1] = m1 + c1[i * 3 + 1];
        x1[i * 3 + 2] = m2 + c1[i * 3 + 2];
    }
    __syncthreads();

    // EdgeConv2 (out dim 1)
    float T2[3], P2[3];
#pragma unroll
    for (int i = 0; i < 3; i++) { T2[i] = t2w[i]; P2[i] = p2w[i]; }
    float B2 = t2b[0] + p2b[0];
    for (int j = tid; j < N_NODES; j += 256) {
        float v0 = x1[j * 3], v1 = x1[j * 3 + 1], v2 = x1[j * 3 + 2];
        float av = T2[0] * v0 + T2[1] * v1 + T2[2] * v2;
        a2[j] = av;
        c2[j] = B2 + P2[0] * v0 + P2[1] * v1 + P2[2] * v2 - av;
    }
    __syncthreads();
    for (int i = tid; i < N_NODES; i += 256) {
        float m = -FLT_MAX;
        const int* sp = src + i * K_DEG;
#pragma unroll
        for (int e = 0; e < K_DEG; e++) m = fmaxf(m, a2[sp[e]]);
        x2[i] = m + c2[i];
    }
    __syncthreads();

    // fc1: [588] -> [10], warp-per-output
    for (int k = warp; k < 10; k += 8) {
        float acc = 0.f;
        for (int j = lane; j < N_NODES; j += 32) acc += x2[j] * fc1w[k * N_NODES + j];
        acc = warp_sum(acc);
        if (lane == 0) y10[k] = lrelu(acc + fc1b[k]);
    }
    __syncthreads();

    // fc2: [10] -> [128]
    if (tid < 128) {
        float acc = fc2b[tid];
#pragma unroll
        for (int j = 0; j < 10; j++) acc += y10[j] * fc2w[tid * 10 + j];
        y128[tid] = lrelu(acc);
    }
    __syncthreads();

    // fc3: [128] -> [256], warp-per-output, float4, 8 outputs in flight
    {
        float4 a4 = ((const float4*)y128)[lane];
#pragma unroll
        for (int pass = 0; pass < 4; pass++) {
            int kb = warp * 32 + pass * 8;
            float acc[8];
#pragma unroll
            for (int q = 0; q < 8; q++) {
                float4 w4 = *((const float4*)(fc3w + (kb + q) * 128) + lane);
                acc[q] = w4.x * a4.x + w4.y * a4.y + w4.z * a4.z + w4.w * a4.w;
            }
#pragma unroll
            for (int q = 0; q < 8; q++) acc[q] = warp_sum(acc[q]);
            if (lane == 0) {
#pragma unroll
                for (int q = 0; q < 8; q++)
                    g_act3[kb + q] = lrelu(acc[q] + fc3b[kb + q]);
            }
        }
    }
}

// ================= K2: fc4 [256]->[512], warp-per-output =================
__global__ void __launch_bounds__(256, 1) k_fc4(
    const float* __restrict__ w, const float* __restrict__ b)
{
    int gw   = blockIdx.x * 8 + (threadIdx.x >> 5);   // 0..511
    int lane = threadIdx.x & 31;
    const float4* wr = (const float4*)(w + gw * 256);
    const float4* ar = (const float4*)g_act3;
    float acc = 0.f;
#pragma unroll
    for (int it = 0; it < 2; it++) {
        float4 w4 = wr[lane + 32 * it];
        float4 a4 = ar[lane + 32 * it];
        acc += w4.x * a4.x + w4.y * a4.y + w4.z * a4.z + w4.w * a4.w;
    }
    acc = warp_sum(acc);
    if (lane == 0) g_act4[gw] = lrelu(acc + b[gw]);
}

// ================= K3: fc5 [512]->[1024], warp-per-output =================
__global__ void __launch_bounds__(256, 1) k_fc5(
    const float* __restrict__ w, const float* __restrict__ b)
{
    int gw   = blockIdx.x * 8 + (threadIdx.x >> 5);   // 0..1023
    int lane = threadIdx.x & 31;
    const float4* wr = (const float4*)(w + gw * 512);
    const float4* ar = (const float4*)g_act4;
    float acc = 0.f;
#pragma unroll
    for (int it = 0; it < 4; it++) {
        float4 w4 = wr[lane + 32 * it];
        float4 a4 = ar[lane + 32 * it];
        acc += w4.x * a4.x + w4.y * a4.y + w4.z * a4.z + w4.w * a4.w;
    }
    acc = warp_sum(acc);
    if (lane == 0) g_act5[gw] = lrelu(acc + b[gw]);
}

// ================= K4: fc6 [1024]->[1764], warp-per-output =================
__global__ void __launch_bounds__(256, 1) k_fc6(
    const float* __restrict__ w, const float* __restrict__ b,
    float* __restrict__ out)
{
    int gw   = blockIdx.x * 8 + (threadIdx.x >> 5);   // 0..1767
    int lane = threadIdx.x & 31;
    if (gw >= 1764) return;
    const float4* wr = (const float4*)(w + (size_t)gw * 1024);
    const float4* ar = (const float4*)g_act5;
    float acc = 0.f;
#pragma unroll
    for (int it = 0; it < 8; it++) {
        float4 w4 = wr[lane + 32 * it];
        float4 a4 = ar[lane + 32 * it];
        acc += w4.x * a4.x + w4.y * a4.y + w4.z * a4.z + w4.w * a4.w;
    }
    acc = warp_sum(acc);
    if (lane == 0) out[gw] = acc + b[gw];
}

extern "C" void kernel_launch(void* const* d_in, const int* in_sizes, int n_in,
                              void* d_out, int out_size) {
    // metadata order:
    // 0 features, 1 src, 2 dst (unused: dst[e] == e/32 by construction),
    // 3 theta1_w, 4 theta1_b, 5 phi1_w, 6 phi1_b,
    // 7 theta2_w, 8 theta2_b, 9 phi2_w, 10 phi2_b,
    // 11 fc1_w, 12 fc1_b, 13 fc2_w, 14 fc2_b, 15 fc3_w, 16 fc3_b,
    // 17 fc4_w, 18 fc4_b, 19 fc5_w, 20 fc5_b, 21 fc6_w, 22 fc6_b
    k_head<<<1, 256>>>(
        (const float*)d_in[0], (const int*)d_in[1],
        (const float*)d_in[3], (const float*)d_in[4],
        (const float*)d_in[5], (const float*)d_in[6],
        (const float*)d_in[7], (const float*)d_in[8],
        (const float*)d_in[9], (const float*)d_in[10],
        (const float*)d_in[11], (const float*)d_in[12],
        (const float*)d_in[13], (const float*)d_in[14],
        (const float*)d_in[15], (const float*)d_in[16]);
    k_fc4<<<64, 256>>>((const float*)d_in[17], (const float*)d_in[18]);
    k_fc5<<<128, 256>>>((const float*)d_in[19], (const float*)d_in[20]);
    k_fc6<<<221, 256>>>((const float*)d_in[21], (const float*)d_in[22], (float*)d_out);
}

// round 6
// speedup vs baseline: 1.8760x; 1.2667x over previous
#include <cuda_runtime.h>
#include <float.h>

#define N_NODES 588
#define K_DEG   32

// -------- global scratch (allocation-free: __device__ arrays) --------
__device__ __align__(16) float g_x1[N_NODES * 3];   // EC1 output
__device__ __align__(16) float g_act3[256];
__device__ __align__(16) float g_act4[512];
__device__ __align__(16) float g_act5[1024];

__device__ __forceinline__ float lrelu(float x) { return x > 0.f ? x : 0.01f * x; }

__device__ __forceinline__ float warp_sum(float v) {
#pragma unroll
    for (int o = 16; o; o >>= 1) v += __shfl_xor_sync(0xffffffffu, v, o);
    return v;
}

// ============ K1: EdgeConv1 — 5 blocks, redundant a1/c1, split gather ============
// Decomposition: msg = a1[src] + c1[dst]; max over src commutes with +c1.
#define EC1_BLKS 5
#define EC1_NPB  118   // nodes per block (5*118 = 590 >= 588)

__global__ void __launch_bounds__(128, 1) k_ec1(
    const float* __restrict__ features, const int* __restrict__ src,
    const float* __restrict__ t1w, const float* __restrict__ t1b,
    const float* __restrict__ p1w, const float* __restrict__ p1b)
{
    const int t = threadIdx.x;
    __shared__ float a1[N_NODES * 3], c1[N_NODES * 3];

    float T1[9], P1[9], B1[3];
#pragma unroll
    for (int i = 0; i < 9; i++) { T1[i] = t1w[i]; P1[i] = p1w[i]; }
#pragma unroll
    for (int i = 0; i < 3; i++) B1[i] = t1b[i] + p1b[i];

    // redundant full a1/c1 (588 nodes over 128 threads, <=5 each)
    for (int j = t; j < N_NODES; j += 128) {
        float v0 = features[j * 3], v1 = features[j * 3 + 1], v2 = features[j * 3 + 2];
#pragma unroll
        for (int k = 0; k < 3; k++) {
            float av = T1[k * 3] * v0 + T1[k * 3 + 1] * v1 + T1[k * 3 + 2] * v2;
            float pv = P1[k * 3] * v0 + P1[k * 3 + 1] * v1 + P1[k * 3 + 2] * v2;
            a1[j * 3 + k] = av;
            c1[j * 3 + k] = B1[k] + pv - av;
        }
    }
    __syncthreads();

    // this block's slice: one node per thread
    int i = blockIdx.x * EC1_NPB + t;
    if (t < EC1_NPB && i < N_NODES) {
        float m0 = -FLT_MAX, m1 = -FLT_MAX, m2 = -FLT_MAX;
        const int* sp = src + i * K_DEG;
#pragma unroll
        for (int e = 0; e < K_DEG; e++) {
            int s = sp[e] * 3;
            m0 = fmaxf(m0, a1[s]);
            m1 = fmaxf(m1, a1[s + 1]);
            m2 = fmaxf(m2, a1[s + 2]);
        }
        g_x1[i * 3]     = m0 + c1[i * 3];
        g_x1[i * 3 + 1] = m1 + c1[i * 3 + 1];
        g_x1[i * 3 + 2] = m2 + c1[i * 3 + 2];
    }
}

// ===== K2: EC2 + fc1 + fc2 (redundant per block) + fc3 (8 rows per block) =====
__global__ void __launch_bounds__(256, 1) k_mid(
    const int* __restrict__ src,
    const float* __restrict__ t2w, const float* __restrict__ t2b,
    const float* __restrict__ p2w, const float* __restrict__ p2b,
    const float* __restrict__ fc1w, const float* __restrict__ fc1b,
    const float* __restrict__ fc2w, const float* __restrict__ fc2b,
    const float* __restrict__ fc3w, const float* __restrict__ fc3b)
{
    const int tid  = threadIdx.x;
    const int warp = tid >> 5;
    const int lane = tid & 31;

    __shared__ float a2[N_NODES], c2[N_NODES], x2[N_NODES];
    __shared__ float y10[10];
    __shared__ __align__(16) float y128[128];

    // EC2 decomposition (redundant): a2/c2 from g_x1
    float T2[3], P2[3];
#pragma unroll
    for (int i = 0; i < 3; i++) { T2[i] = t2w[i]; P2[i] = p2w[i]; }
    float B2 = t2b[0] + p2b[0];
    for (int j = tid; j < N_NODES; j += 256) {
        float v0 = g_x1[j * 3], v1 = g_x1[j * 3 + 1], v2 = g_x1[j * 3 + 2];
        float av = T2[0] * v0 + T2[1] * v1 + T2[2] * v2;
        a2[j] = av;
        c2[j] = B2 + P2[0] * v0 + P2[1] * v1 + P2[2] * v2 - av;
    }
    __syncthreads();

    // segment-max (redundant)
    for (int i = tid; i < N_NODES; i += 256) {
        float m = -FLT_MAX;
        const int* sp = src + i * K_DEG;
#pragma unroll
        for (int e = 0; e < K_DEG; e++) m = fmaxf(m, a2[sp[e]]);
        x2[i] = m + c2[i];
    }
    __syncthreads();

    // fc1: [588]->[10], warp-per-output (redundant), fully unrolled trip count.
    // 588 = 18*32 + 12: 18 full strides for all lanes, 19th only for lane < 12.
    for (int k = warp; k < 10; k += 8) {
        const float* wrow = fc1w + k * N_NODES;
        float acc = 0.f;
#pragma unroll
        for (int it = 0; it < 18; it++) {
            int j = it * 32 + lane;
            acc += x2[j] * wrow[j];
        }
        if (lane < 12) {
            int j = 18 * 32 + lane;
            acc += x2[j] * wrow[j];
        }
        acc = warp_sum(acc);
        if (lane == 0) y10[k] = lrelu(acc + fc1b[k]);
    }
    __syncthreads();

    // fc2: [10]->[128] (redundant)
    if (tid < 128) {
        float acc = fc2b[tid];
#pragma unroll
        for (int j = 0; j < 10; j++) acc += y10[j] * fc2w[tid * 10 + j];
        y128[tid] = lrelu(acc);
    }
    __syncthreads();

    // fc3: this block's 8 rows, warp-per-output, single pass
    {
        int k = blockIdx.x * 8 + warp;                 // < 256
        float4 a4 = ((const float4*)y128)[lane];
        float4 w4 = *((const float4*)(fc3w + k * 128) + lane);
        float acc = w4.x * a4.x + w4.y * a4.y + w4.z * a4.z + w4.w * a4.w;
        acc = warp_sum(acc);
        if (lane == 0) g_act3[k] = lrelu(acc + fc3b[k]);
    }
}

// ================= K3: fc4 [256]->[512], warp-per-output =================
__global__ void __launch_bounds__(256, 1) k_fc4(
    const float* __restrict__ w, const float* __restrict__ b)
{
    int gw   = blockIdx.x * 8 + (threadIdx.x >> 5);   // 0..511
    int lane = threadIdx.x & 31;
    const float4* wr = (const float4*)(w + gw * 256);
    const float4* ar = (const float4*)g_act3;
    float acc = 0.f;
#pragma unroll
    for (int it = 0; it < 2; it++) {
        float4 w4 = wr[lane + 32 * it];
        float4 a4 = ar[lane + 32 * it];
        acc += w4.x * a4.x + w4.y * a4.y + w4.z * a4.z + w4.w * a4.w;
    }
    acc = warp_sum(acc);
    if (lane == 0) g_act4[gw] = lrelu(acc + b[gw]);
}

// ================= K4: fc5 [512]->[1024], warp-per-output =================
__global__ void __launch_bounds__(256, 1) k_fc5(
    const float* __restrict__ w, const float* __restrict__ b)
{
    int gw   = blockIdx.x * 8 + (threadIdx.x >> 5);   // 0..1023
    int lane = threadIdx.x & 31;
    const float4* wr = (const float4*)(w + gw * 512);
    const float4* ar = (const float4*)g_act4;
    float acc = 0.f;
#pragma unroll
    for (int it = 0; it < 4; it++) {
        float4 w4 = wr[lane + 32 * it];
        float4 a4 = ar[lane + 32 * it];
        acc += w4.x * a4.x + w4.y * a4.y + w4.z * a4.z + w4.w * a4.w;
    }
    acc = warp_sum(acc);
    if (lane == 0) g_act5[gw] = lrelu(acc + b[gw]);
}

// ================= K5: fc6 [1024]->[1764], warp-per-output =================
__global__ void __launch_bounds__(256, 1) k_fc6(
    const float* __restrict__ w, const float* __restrict__ b,
    float* __restrict__ out)
{
    int gw   = blockIdx.x * 8 + (threadIdx.x >> 5);   // 0..1767
    int lane = threadIdx.x & 31;
    if (gw >= 1764) return;
    const float4* wr = (const float4*)(w + (size_t)gw * 1024);
    const float4* ar = (const float4*)g_act5;
    float acc = 0.f;
#pragma unroll
    for (int it = 0; it < 8; it++) {
        float4 w4 = wr[lane + 32 * it];
        float4 a4 = ar[lane + 32 * it];
        acc += w4.x * a4.x + w4.y * a4.y + w4.z * a4.z + w4.w * a4.w;
    }
    acc = warp_sum(acc);
    if (lane == 0) out[gw] = acc + b[gw];
}

extern "C" void kernel_launch(void* const* d_in, const int* in_sizes, int n_in,
                              void* d_out, int out_size) {
    // metadata order:
    // 0 features, 1 src, 2 dst (unused: dst[e] == e/32 by construction),
    // 3 theta1_w, 4 theta1_b, 5 phi1_w, 6 phi1_b,
    // 7 theta2_w, 8 theta2_b, 9 phi2_w, 10 phi2_b,
    // 11 fc1_w, 12 fc1_b, 13 fc2_w, 14 fc2_b, 15 fc3_w, 16 fc3_b,
    // 17 fc4_w, 18 fc4_b, 19 fc5_w, 20 fc5_b, 21 fc6_w, 22 fc6_b
    k_ec1<<<EC1_BLKS, 128>>>(
        (const float*)d_in[0], (const int*)d_in[1],
        (const float*)d_in[3], (const float*)d_in[4],
        (const float*)d_in[5], (const float*)d_in[6]);
    k_mid<<<32, 256>>>(
        (const int*)d_in[1],
        (const float*)d_in[7], (const float*)d_in[8],
        (const float*)d_in[9], (const float*)d_in[10],
        (const float*)d_in[11], (const float*)d_in[12],
        (const float*)d_in[13], (const float*)d_in[14],
        (const float*)d_in[15], (const float*)d_in[16]);
    k_fc4<<<64, 256>>>((const float*)d_in[17], (const float*)d_in[18]);
    k_fc5<<<128, 256>>>((const float*)d_in[19], (const float*)d_in[20]);
    k_fc6<<<221, 256>>>((const float*)d_in[21], (const float*)d_in[22], (float*)d_out);
}

// round 7
// speedup vs baseline: 2.1415x; 1.1415x over previous
#include <cuda_runtime.h>
#include <float.h>

#define N_NODES 588
#define K_DEG   32

// -------- global scratch (allocation-free: __device__ arrays) --------
__device__ __align__(16) float g_x1[N_NODES * 3];   // EC1 output
__device__ __align__(16) float g_act3[256];
__device__ __align__(16) float g_act4[512];
__device__ __align__(16) float g_act5[1024];

__device__ __forceinline__ float lrelu(float x) { return x > 0.f ? x : 0.01f * x; }

__device__ __forceinline__ float warp_sum(float v) {
#pragma unroll
    for (int o = 16; o; o >>= 1) v += __shfl_xor_sync(0xffffffffu, v, o);
    return v;
}

// PDL primitives: wait for programmatic predecessor's data; signal dependents.
__device__ __forceinline__ void pdl_wait()   { asm volatile("griddepcontrol.wait;" ::: "memory"); }
__device__ __forceinline__ void pdl_launch() { asm volatile("griddepcontrol.launch_dependents;" ::: "memory"); }

// ============ K1: EdgeConv1 — 5 blocks, redundant a1/c1, split gather ============
// Decomposition: msg = a1[src] + c1[dst]; max over src commutes with +c1.
#define EC1_BLKS 5
#define EC1_NPB  118   // nodes per block (5*118 = 590 >= 588)

__global__ void __launch_bounds__(128, 1) k_ec1(
    const float* __restrict__ features, const int* __restrict__ src,
    const float* __restrict__ t1w, const float* __restrict__ t1b,
    const float* __restrict__ p1w, const float* __restrict__ p1b)
{
    const int t = threadIdx.x;
    __shared__ float a1[N_NODES * 3], c1[N_NODES * 3];

    // reads only external inputs -> no pdl_wait needed
    float T1[9], P1[9], B1[3];
#pragma unroll
    for (int i = 0; i < 9; i++) { T1[i] = t1w[i]; P1[i] = p1w[i]; }
#pragma unroll
    for (int i = 0; i < 3; i++) B1[i] = t1b[i] + p1b[i];

    for (int j = t; j < N_NODES; j += 128) {
        float v0 = features[j * 3], v1 = features[j * 3 + 1], v2 = features[j * 3 + 2];
#pragma unroll
        for (int k = 0; k < 3; k++) {
            float av = T1[k * 3] * v0 + T1[k * 3 + 1] * v1 + T1[k * 3 + 2] * v2;
            float pv = P1[k * 3] * v0 + P1[k * 3 + 1] * v1 + P1[k * 3 + 2] * v2;
            a1[j * 3 + k] = av;
            c1[j * 3 + k] = B1[k] + pv - av;
        }
    }
    __syncthreads();

    int i = blockIdx.x * EC1_NPB + t;
    if (t < EC1_NPB && i < N_NODES) {
        float m0 = -FLT_MAX, m1 = -FLT_MAX, m2 = -FLT_MAX;
        const int* sp = src + i * K_DEG;
#pragma unroll
        for (int e = 0; e < K_DEG; e++) {
            int s = sp[e] * 3;
            m0 = fmaxf(m0, a1[s]);
            m1 = fmaxf(m1, a1[s + 1]);
            m2 = fmaxf(m2, a1[s + 2]);
        }
        g_x1[i * 3]     = m0 + c1[i * 3];
        g_x1[i * 3 + 1] = m1 + c1[i * 3 + 1];
        g_x1[i * 3 + 2] = m2 + c1[i * 3 + 2];
    }
    pdl_launch();
}

// ===== K2: EC2 + fc1 + fc2 (redundant per block) + fc3 (8 rows per block) =====
__global__ void __launch_bounds__(256, 1) k_mid(
    const int* __restrict__ src,
    const float* __restrict__ t2w, const float* __restrict__ t2b,
    const float* __restrict__ p2w, const float* __restrict__ p2b,
    const float* __restrict__ fc1w, const float* __restrict__ fc1b,
    const float* __restrict__ fc2w, const float* __restrict__ fc2b,
    const float* __restrict__ fc3w, const float* __restrict__ fc3b)
{
    const int tid  = threadIdx.x;
    const int warp = tid >> 5;
    const int lane = tid & 31;

    __shared__ float a2[N_NODES], c2[N_NODES], x2[N_NODES];
    __shared__ float y10[10];
    __shared__ __align__(16) float y128[128];

    // ---- pre-wait prologue: everything that reads only external inputs ----
    float T2[3], P2[3];
#pragma unroll
    for (int i = 0; i < 3; i++) { T2[i] = t2w[i]; P2[i] = p2w[i]; }
    float B2 = t2b[0] + p2b[0];
    // preload this block's fc3 row + fc2 row slice into registers
    int k3 = blockIdx.x * 8 + warp;                    // < 256
    float4 w3 = *((const float4*)(fc3w + k3 * 128) + lane);
    float b3 = fc3b[k3];

    pdl_wait();   // g_x1 ready from here on

    // EC2 decomposition (redundant): a2/c2 from g_x1
    for (int j = tid; j < N_NODES; j += 256) {
        float v0 = g_x1[j * 3], v1 = g_x1[j * 3 + 1], v2 = g_x1[j * 3 + 2];
        float av = T2[0] * v0 + T2[1] * v1 + T2[2] * v2;
        a2[j] = av;
        c2[j] = B2 + P2[0] * v0 + P2[1] * v1 + P2[2] * v2 - av;
    }
    __syncthreads();

    // segment-max (redundant)
    for (int i = tid; i < N_NODES; i += 256) {
        float m = -FLT_MAX;
        const int* sp = src + i * K_DEG;
#pragma unroll
        for (int e = 0; e < K_DEG; e++) m = fmaxf(m, a2[sp[e]]);
        x2[i] = m + c2[i];
    }
    __syncthreads();

    // fc1: [588]->[10], warp-per-output (redundant), fully unrolled.
    // 588 = 18*32 + 12: 18 full strides, 19th only for lane < 12.
    for (int k = warp; k < 10; k += 8) {
        const float* wrow = fc1w + k * N_NODES;
        float acc = 0.f;
#pragma unroll
        for (int it = 0; it < 18; it++) {
            int j = it * 32 + lane;
            acc += x2[j] * wrow[j];
        }
        if (lane < 12) {
            int j = 18 * 32 + lane;
            acc += x2[j] * wrow[j];
        }
        acc = warp_sum(acc);
        if (lane == 0) y10[k] = lrelu(acc + fc1b[k]);
    }
    __syncthreads();

    // fc2: [10]->[128] (redundant)
    if (tid < 128) {
        float acc = fc2b[tid];
#pragma unroll
        for (int j = 0; j < 10; j++) acc += y10[j] * fc2w[tid * 10 + j];
        y128[tid] = lrelu(acc);
    }
    __syncthreads();

    // fc3: this block's 8 rows, warp-per-output, single pass (weights preloaded)
    {
        float4 a4 = ((const float4*)y128)[lane];
        float acc = w3.x * a4.x + w3.y * a4.y + w3.z * a4.z + w3.w * a4.w;
        acc = warp_sum(acc);
        if (lane == 0) g_act3[k3] = lrelu(acc + b3);
    }
    pdl_launch();
}

// ================= K3: fc4 [256]->[512], warp-per-output =================
__global__ void __launch_bounds__(256, 1) k_fc4(
    const float* __restrict__ w, const float* __restrict__ b)
{
    int gw   = blockIdx.x * 8 + (threadIdx.x >> 5);   // 0..511
    int lane = threadIdx.x & 31;
    // pre-wait: weights + bias
    const float4* wr = (const float4*)(w + gw * 256);
    float4 W[2];
#pragma unroll
    for (int it = 0; it < 2; it++) W[it] = wr[lane + 32 * it];
    float bb = b[gw];

    pdl_wait();   // g_act3 ready

    const float4* ar = (const float4*)g_act3;
    float acc = 0.f;
#pragma unroll
    for (int it = 0; it < 2; it++) {
        float4 a4 = ar[lane + 32 * it];
        acc += W[it].x * a4.x + W[it].y * a4.y + W[it].z * a4.z + W[it].w * a4.w;
    }
    acc = warp_sum(acc);
    if (lane == 0) g_act4[gw] = lrelu(acc + bb);
    pdl_launch();
}

// ================= K4: fc5 [512]->[1024], warp-per-output =================
__global__ void __launch_bounds__(256, 1) k_fc5(
    const float* __restrict__ w, const float* __restrict__ b)
{
    int gw   = blockIdx.x * 8 + (threadIdx.x >> 5);   // 0..1023
    int lane = threadIdx.x & 31;
    const float4* wr = (const float4*)(w + gw * 512);
    float4 W[4];
#pragma unroll
    for (int it = 0; it < 4; it++) W[it] = wr[lane + 32 * it];
    float bb = b[gw];

    pdl_wait();   // g_act4 ready

    const float4* ar = (const float4*)g_act4;
    float acc = 0.f;
#pragma unroll
    for (int it = 0; it < 4; it++) {
        float4 a4 = ar[lane + 32 * it];
        acc += W[it].x * a4.x + W[it].y * a4.y + W[it].z * a4.z + W[it].w * a4.w;
    }
    acc = warp_sum(acc);
    if (lane == 0) g_act5[gw] = lrelu(acc + bb);
    pdl_launch();
}

// ================= K5: fc6 [1024]->[1764], warp-per-output =================
__global__ void __launch_bounds__(256, 1) k_fc6(
    const float* __restrict__ w, const float* __restrict__ b,
    float* __restrict__ out)
{
    int gw   = blockIdx.x * 8 + (threadIdx.x >> 5);   // 0..1767
    int lane = threadIdx.x & 31;
    if (gw >= 1764) return;
    const float4* wr = (const float4*)(w + (size_t)gw * 1024);
    float4 W[8];
#pragma unroll
    for (int it = 0; it < 8; it++) W[it] = wr[lane + 32 * it];
    float bb = b[gw];

    pdl_wait();   // g_act5 ready

    const float4* ar = (const float4*)g_act5;
    float acc = 0.f;
#pragma unroll
    for (int it = 0; it < 8; it++) {
        float4 a4 = ar[lane + 32 * it];
        acc += W[it].x * a4.x + W[it].y * a4.y + W[it].z * a4.z + W[it].w * a4.w;
    }
    acc = warp_sum(acc);
    if (lane == 0) out[gw] = acc + bb;
}

// -------- host-side PDL launch helper --------
template <typename... Args>
static void launch_pdl(void (*kern)(Args...), dim3 grid, dim3 blk, Args... args) {
    cudaLaunchConfig_t cfg = {};
    cfg.gridDim = grid;
    cfg.blockDim = blk;
    cfg.dynamicSmemBytes = 0;
    cfg.stream = 0;   // legacy default stream (same one the harness captures)
    cudaLaunchAttribute attr[1];
    attr[0].id = cudaLaunchAttributeProgrammaticStreamSerialization;
    attr[0].val.programmaticStreamSerializationAllowed = 1;
    cfg.attrs = attr;
    cfg.numAttrs = 1;
    cudaLaunchKernelEx(&cfg, kern, args...);
}

extern "C" void kernel_launch(void* const* d_in, const int* in_sizes, int n_in,
                              void* d_out, int out_size) {
    // metadata order:
    // 0 features, 1 src, 2 dst (unused: dst[e] == e/32 by construction),
    // 3 theta1_w, 4 theta1_b, 5 phi1_w, 6 phi1_b,
    // 7 theta2_w, 8 theta2_b, 9 phi2_w, 10 phi2_b,
    // 11 fc1_w, 12 fc1_b, 13 fc2_w, 14 fc2_b, 15 fc3_w, 16 fc3_b,
    // 17 fc4_w, 18 fc4_b, 19 fc5_w, 20 fc5_b, 21 fc6_w, 22 fc6_b
    launch_pdl(k_ec1, dim3(EC1_BLKS), dim3(128),
        (const float*)d_in[0], (const int*)d_in[1],
        (const float*)d_in[3], (const float*)d_in[4],
        (const float*)d_in[5], (const float*)d_in[6]);
    launch_pdl(k_mid, dim3(32), dim3(256),
        (const int*)d_in[1],
        (const float*)d_in[7], (const float*)d_in[8],
        (const float*)d_in[9], (const float*)d_in[10],
        (const float*)d_in[11], (const float*)d_in[12],
        (const float*)d_in[13], (const float*)d_in[14],
        (const float*)d_in[15], (const float*)d_in[16]);
    launch_pdl(k_fc4, dim3(64), dim3(256),
        (const float*)d_in[17], (const float*)d_in[18]);
    launch_pdl(k_fc5, dim3(128), dim3(256),
        (const float*)d_in[19], (const float*)d_in[20]);
    launch_pdl(k_fc6, dim3(221), dim3(256),
        (const float*)d_in[21], (const float*)d_in[22], (float*)d_out);
}